// round 6
// baseline (speedup 1.0000x reference)
#include <cuda_runtime.h>

#define BATCH 32
#define HH 1024
#define WW 1024
#define WPR 32
#define WORDS_PER_IMG (HH * WPR)         // 32768
#define NWORDS (BATCH * WORDS_PER_IMG)   // 1048576
#define NCELLS (BATCH * HH * WW)         // 33554432

#define NPACK 16384                      // pack-initial blocks (2 rows each)
#define NSIM  512                        // sim blocks (1 tile each)
#define NCOPY 16384                      // target copy+pack blocks (2 rows each)

#define TH 64
#define SH (TH + 16)
#define SW 34

__device__ unsigned g_A[NWORDS];         // packed initial state
__device__ unsigned g_T[NWORDS];         // packed target
__device__ unsigned g_readyA[NSIM];      // per-tile pack coverage counters
__device__ unsigned g_readyT[NSIM];      // per-tile target-bits coverage counters
__device__ unsigned long long g_live;
__device__ unsigned long long g_mism;
__device__ unsigned g_done;

__device__ __forceinline__ void hsum(unsigned l, unsigned m, unsigned r,
                                     unsigned& h0, unsigned& h1) {
    unsigned L = __funnelshift_l(l, m, 1);
    unsigned R = __funnelshift_r(m, r, 1);
    unsigned t = L ^ R;
    h0 = t ^ m;
    h1 = (L & R) | (t & m);
}

__device__ __forceinline__ unsigned gol_combine(
    unsigned h0a, unsigned h1a, unsigned h0b, unsigned h1b,
    unsigned h0c, unsigned h1c, unsigned bm) {
    unsigned t  = h0a ^ h0b;
    unsigned s0 = t ^ h0c;
    unsigned c1 = (h0a & h0b) | (t & h0c);
    unsigned u  = h1a ^ h1b;
    unsigned p  = u ^ h1c;
    unsigned q  = (h1a & h1b) | (u & h1c);
    unsigned s1 = p ^ c1;
    unsigned c2 = p & c1;
    unsigned eq3 = s0 & s1 & ~(q | c2);
    unsigned eq4 = (q ^ c2) & ~(s0 | s1);
    return eq3 | (bm & eq4);
}

__global__ __launch_bounds__(256) void k_gol(const float* __restrict__ ini,
                                             const float* __restrict__ tgt,
                                             float* __restrict__ out) {
    __shared__ unsigned sb[2][SH][SW];
    __shared__ int sh_live[8], sh_mism[8];
    __shared__ int sh_last;

    int tid  = threadIdx.x;
    int lane = tid & 31;
    int wrp  = tid >> 5;

    if (blockIdx.x < NPACK) {
        // ================= pack initial role =================
        int b2 = blockIdx.x;                       // covers cells [b2*2048, +2048)
        const float4* p = (const float4*)(ini + (size_t)b2 * 2048);
        float4 f1 = p[tid * 2];
        float4 f2 = p[tid * 2 + 1];
        unsigned byte =
              (f1.x > 0.5f ? 1u : 0u) | (f1.y > 0.5f ? 2u : 0u)
            | (f1.z > 0.5f ? 4u : 0u) | (f1.w > 0.5f ? 8u : 0u)
            | (f2.x > 0.5f ? 16u : 0u) | (f2.y > 0.5f ? 32u : 0u)
            | (f2.z > 0.5f ? 64u : 0u) | (f2.w > 0.5f ? 128u : 0u);
        unsigned v = byte << ((lane & 3) * 8);
        v |= __shfl_xor_sync(0xffffffffu, v, 1);
        v |= __shfl_xor_sync(0xffffffffu, v, 2);
        if ((lane & 3) == 0)
            g_A[b2 * 64 + wrp * 8 + (lane >> 2)] = v;

        __threadfence();
        __syncthreads();
        if (tid == 0) {
            int b = b2 >> 9;                       // image
            int j = b2 & 511;                      // row pair within image
            int lo = (j - 4) / 32; if (lo < 0) lo = 0;
            int hi = (j + 4) / 32; if (hi > 15) hi = 15;
            for (int ty = lo; ty <= hi; ++ty)
                atomicAdd(&g_readyA[b * 16 + ty], 1u);
        }
        return;
    }

    if (blockIdx.x >= NPACK + NSIM) {
        // ================= target copy + pack role =================
        int cblk = blockIdx.x - (NPACK + NSIM);
        int warp = cblk * 8 + wrp;
        unsigned cb = (unsigned)warp * 256u;
        unsigned wb = (unsigned)warp * 8u;
        float* out_tgt = out + 1 + (size_t)NCELLS;

        float ft[8];
        #pragma unroll
        for (int k = 0; k < 8; ++k) ft[k] = tgt[cb + 32u * k + lane];
        #pragma unroll
        for (int k = 0; k < 8; ++k) out_tgt[cb + 32u * k + lane] = ft[k];

        unsigned myw = 0u;
        #pragma unroll
        for (int k = 0; k < 8; ++k) {
            unsigned bT = __ballot_sync(0xffffffffu, ft[k] > 0.5f);
            if (lane == k) myw = bT;
        }
        if (lane < 8) g_T[wb + lane] = myw;

        __threadfence();
        __syncthreads();
        if (tid == 0) {
            int b = cblk >> 9;
            int j = cblk & 511;                    // row pair; interior tile = j>>5
            atomicAdd(&g_readyT[b * 16 + (j >> 5)], 1u);
        }
        return;
    }

    // ================= life simulation role =================
    int s  = blockIdx.x - NPACK;          // tile id 0..511
    int b  = s >> 4;
    int ty = s & 15;
    int r0 = ty * TH;

    // wait for our tile+halo of g_A (producers have lower blockIdx; never wait)
    if (tid == 0) {
        unsigned need = (ty == 0 || ty == 15) ? 36u : 40u;
        while (atomicAdd(&g_readyA[s], 0u) < need) __nanosleep(128);
    }
    __syncthreads();

    const unsigned* img = g_A + b * WORDS_PER_IMG;

    for (int sr = tid; sr < SH; sr += 256) {
        sb[0][sr][0] = 0u; sb[0][sr][33] = 0u;
        sb[1][sr][0] = 0u; sb[1][sr][33] = 0u;
    }
    for (int idx = tid; idx < SH * 32; idx += 256) {
        int sr = idx >> 5;
        int c  = idx & 31;
        int gr = r0 - 8 + sr;
        unsigned v = ((unsigned)gr < (unsigned)HH) ? __ldcg(&img[gr * WPR + c]) : 0u;
        sb[0][sr][c + 1] = v;
    }
    __syncthreads();

    int c      = tid & 31;
    int strip  = tid >> 5;
    int rstart = 1 + strip * 10;
    int rend   = (rstart + 10 < 79) ? (rstart + 10) : 79;

    #pragma unroll
    for (int g = 0; g < 8; ++g) {
        int cur = g & 1, nxt = cur ^ 1;

        unsigned h0a, h1a, h0b, h1b, h0c, h1c;
        hsum(sb[cur][rstart - 1][c], sb[cur][rstart - 1][c + 1], sb[cur][rstart - 1][c + 2], h0a, h1a);
        unsigned bm = sb[cur][rstart][c + 1];
        hsum(sb[cur][rstart][c], bm, sb[cur][rstart][c + 2], h0b, h1b);

        for (int r = rstart; r < rend; ++r) {
            unsigned nl = sb[cur][r + 1][c];
            unsigned nm = sb[cur][r + 1][c + 1];
            unsigned nr = sb[cur][r + 1][c + 2];
            hsum(nl, nm, nr, h0c, h1c);

            unsigned next = gol_combine(h0a, h1a, h0b, h1b, h0c, h1c, bm);
            if ((unsigned)(r0 - 8 + r) >= (unsigned)HH) next = 0u;
            sb[nxt][r][c + 1] = next;

            h0a = h0b; h1a = h1b;
            h0b = h0c; h1b = h1c;
            bm  = nm;
        }
        __syncthreads();
    }
    // final state in sb[0], interior rows [8,72)

    // write state floats straight from smem (coalesced STG.32, LDS broadcast)
    float* outs = out + 1 + ((size_t)b * HH + r0) * WW;
    #pragma unroll 4
    for (int i = tid; i < TH * 1024; i += 256) {
        int row = i >> 10;
        int wc  = (i & 1023) >> 5;                 // uniform per warp
        unsigned w = sb[0][8 + row][wc + 1];
        outs[i] = __uint_as_float(((w >> lane) & 1u) * 0x3f800000u);
    }

    // wait for target bits of this tile, then popc reduce
    if (tid == 0) {
        while (atomicAdd(&g_readyT[s], 0u) < 32u) __nanosleep(128);
    }
    __syncthreads();

    const unsigned* tw = g_T + b * WORDS_PER_IMG + r0 * WPR;
    int live = 0, mism = 0;
    #pragma unroll
    for (int k = 0; k < 8; ++k) {
        int widx = tid + 256 * k;
        int row  = widx >> 5, col = widx & 31;
        unsigned w = sb[0][8 + row][col + 1];
        unsigned t = __ldcg(&tw[widx]);
        live += __popc(w);
        mism += __popc(w ^ t);
    }

    #pragma unroll
    for (int o = 16; o > 0; o >>= 1) {
        live += __shfl_down_sync(0xffffffffu, live, o);
        mism += __shfl_down_sync(0xffffffffu, mism, o);
    }
    if (lane == 0) { sh_live[wrp] = live; sh_mism[wrp] = mism; }
    __syncthreads();
    if (tid == 0) {
        int L = 0, M = 0;
        #pragma unroll
        for (int k = 0; k < 8; ++k) { L += sh_live[k]; M += sh_mism[k]; }
        atomicAdd(&g_live, (unsigned long long)L);
        atomicAdd(&g_mism, (unsigned long long)M);
        __threadfence();
        unsigned prev = atomicAdd(&g_done, 1u);
        sh_last = (prev == (unsigned)(NSIM - 1)) ? 1 : 0;
    }
    __syncthreads();
    if (sh_last) {
        // last sim block: finalize scalars + self-reset all counters for replay
        for (int i = tid; i < NSIM; i += 256) {
            g_readyA[i] = 0u;
            g_readyT[i] = 0u;
        }
        if (tid == 0) {
            unsigned long long mt = atomicAdd(&g_mism, 0ull);
            unsigned long long lt = atomicAdd(&g_live, 0ull);
            out[0]              = (float)((double)mt / (double)NCELLS);  // loss
            out[1 + 2 * NCELLS] = (float)lt;                             // live_cells
            out[2 + 2 * NCELLS] = mt ? 1.0f : 0.0f;                      // max_abs_error
            g_live = 0ull; g_mism = 0ull;
            __threadfence();
            g_done = 0u;
        }
    }
}

extern "C" void kernel_launch(void* const* d_in, const int* in_sizes, int n_in,
                              void* d_out, int out_size) {
    const float* initial = (const float*)d_in[0];
    const float* target  = (const float*)d_in[1];
    (void)in_sizes; (void)n_in; (void)out_size;   // generations fixed at 8

    k_gol<<<NPACK + NSIM + NCOPY, 256>>>(initial, target, (float*)d_out);
}

// round 7
// speedup vs baseline: 1.0308x; 1.0308x over previous
#include <cuda_runtime.h>

#define BATCH 32
#define HH 1024
#define WW 1024
#define WPR 32
#define WORDS_PER_IMG (HH * WPR)
#define NWORDS (BATCH * WORDS_PER_IMG)   // 1048576
#define NCELLS (BATCH * HH * WW)         // 33554432

#define TH 64
#define SH (TH + 16)
#define SW 34
#define NSIM  (BATCH * (HH / TH))        // 512 sim blocks
#define NCOPY 16384                      // target copy blocks (2048 cells each)
#define NUNP  8192                       // unpack blocks (4096 cells each)
#define NQ    ((NCELLS - 4) / 4 + 1)     // 8388607 shifted quads in [3, NCELLS-1)

__device__ unsigned g_A[NWORDS];
__device__ unsigned g_B[NWORDS];
__device__ unsigned g_T[NWORDS];
__device__ unsigned long long g_live;
__device__ unsigned long long g_mism;
__device__ unsigned g_done;

// ---------------------------------------------------------------------------
// K1: pack initial floats -> bits. Thread: 8 cells via 2x LDG.128.
// ---------------------------------------------------------------------------
__global__ __launch_bounds__(256) void k_pack_ini(const float* __restrict__ ini) {
    int tid  = threadIdx.x;
    int lane = tid & 31;
    int wrp  = tid >> 5;
    int b2   = blockIdx.x;                       // 2048 cells per block
    const float4* p = (const float4*)(ini + (size_t)b2 * 2048);
    float4 f1 = p[tid * 2];
    float4 f2 = p[tid * 2 + 1];
    unsigned byte =
          (f1.x > 0.5f ? 1u : 0u)  | (f1.y > 0.5f ? 2u : 0u)
        | (f1.z > 0.5f ? 4u : 0u)  | (f1.w > 0.5f ? 8u : 0u)
        | (f2.x > 0.5f ? 16u : 0u) | (f2.y > 0.5f ? 32u : 0u)
        | (f2.z > 0.5f ? 64u : 0u) | (f2.w > 0.5f ? 128u : 0u);
    unsigned v = byte << ((lane & 3) * 8);
    v |= __shfl_xor_sync(0xffffffffu, v, 1);
    v |= __shfl_xor_sync(0xffffffffu, v, 2);
    if ((lane & 3) == 0)
        g_A[b2 * 64 + wrp * 8 + (lane >> 2)] = v;
}

// ---------------------------------------------------------------------------
// K2: blocks [0,512): 8-gen bit-sliced life (g_A -> g_B).
//     blocks [512,...): target copy (vectorized, shifted stores) + pack g_T.
// ---------------------------------------------------------------------------
__device__ __forceinline__ void hsum(unsigned l, unsigned m, unsigned r,
                                     unsigned& h0, unsigned& h1) {
    unsigned L = __funnelshift_l(l, m, 1);
    unsigned R = __funnelshift_r(m, r, 1);
    unsigned t = L ^ R;
    h0 = t ^ m;
    h1 = (L & R) | (t & m);
}

__device__ __forceinline__ unsigned gol_combine(
    unsigned h0a, unsigned h1a, unsigned h0b, unsigned h1b,
    unsigned h0c, unsigned h1c, unsigned bm) {
    unsigned t  = h0a ^ h0b;
    unsigned s0 = t ^ h0c;
    unsigned c1 = (h0a & h0b) | (t & h0c);
    unsigned u  = h1a ^ h1b;
    unsigned p  = u ^ h1c;
    unsigned q  = (h1a & h1b) | (u & h1c);
    unsigned s1 = p ^ c1;
    unsigned c2 = p & c1;
    unsigned eq3 = s0 & s1 & ~(q | c2);
    unsigned eq4 = (q ^ c2) & ~(s0 | s1);
    return eq3 | (bm & eq4);
}

__global__ __launch_bounds__(256) void k_life_tgt(const float* __restrict__ tgt,
                                                  float* __restrict__ out) {
    int tid  = threadIdx.x;
    int lane = tid & 31;
    int wrp  = tid >> 5;

    if (blockIdx.x >= NSIM) {
        // ================= target copy + pack role =================
        int cblk = blockIdx.x - NSIM;
        int C    = cblk * 2048;                         // cell base
        const float4* t4 = (const float4*)tgt;
        float* outt = out + 1 + (size_t)NCELLS;

        #pragma unroll
        for (int j = 0; j < 2; ++j) {
            int qidx = (C >> 2) + wrp * 64 + j * 32 + lane;
            float4 f = t4[qidx];

            // neighbor quad (lane+1); lane 31 loads it (guard global end)
            float4 fn;
            fn.x = __shfl_down_sync(0xffffffffu, f.x, 1);
            fn.y = __shfl_down_sync(0xffffffffu, f.y, 1);
            fn.z = __shfl_down_sync(0xffffffffu, f.z, 1);
            fn.w = __shfl_down_sync(0xffffffffu, f.w, 1);
            if (lane == 31) {
                int nq = qidx + 1;
                if (nq < NCELLS / 4) fn = t4[nq];
                else fn = make_float4(0.f, 0.f, 0.f, 0.f);
            }

            // shifted store: quad at out cells [scell, scell+4)
            int scell = C + wrp * 256 + j * 128 + 4 * lane + 3;
            if (scell != NCELLS - 1) {
                float4 g = make_float4(f.w, fn.x, fn.y, fn.z);
                *(float4*)(outt + scell) = g;
            } else {
                outt[scell] = f.w;                      // global tail (1 cell)
            }
            if (cblk == 0 && wrp == 0 && j == 0 && lane == 0) {
                outt[0] = f.x; outt[1] = f.y; outt[2] = f.z;   // global head
            }

            // pack target bits (unshifted)
            unsigned nib = (f.x > 0.5f ? 1u : 0u) | (f.y > 0.5f ? 2u : 0u)
                         | (f.z > 0.5f ? 4u : 0u) | (f.w > 0.5f ? 8u : 0u);
            unsigned v = nib << ((lane & 7) * 4);
            v |= __shfl_xor_sync(0xffffffffu, v, 1);
            v |= __shfl_xor_sync(0xffffffffu, v, 2);
            v |= __shfl_xor_sync(0xffffffffu, v, 4);
            if ((lane & 7) == 0)
                g_T[(C >> 5) + wrp * 8 + j * 4 + (lane >> 3)] = v;
        }
        return;
    }

    // ================= life simulation role =================
    __shared__ unsigned sb[2][SH][SW];

    int tile = blockIdx.x;
    int b    = tile >> 4;
    int ty   = tile & 15;
    int r0   = ty * TH;

    const unsigned* img = g_A + b * WORDS_PER_IMG;

    for (int s = tid; s < SH; s += 256) {
        sb[0][s][0] = 0u; sb[0][s][33] = 0u;
        sb[1][s][0] = 0u; sb[1][s][33] = 0u;
    }
    for (int idx = tid; idx < SH * 32; idx += 256) {
        int s  = idx >> 5;
        int c  = idx & 31;
        int gr = r0 - 8 + s;
        unsigned v = ((unsigned)gr < (unsigned)HH) ? img[gr * WPR + c] : 0u;
        sb[0][s][c + 1] = v;
    }
    __syncthreads();

    int c      = tid & 31;
    int strip  = tid >> 5;
    int rstart = 1 + strip * 10;
    int rend   = (rstart + 10 < 79) ? (rstart + 10) : 79;

    #pragma unroll
    for (int g = 0; g < 8; ++g) {
        int cur = g & 1, nxt = cur ^ 1;

        unsigned h0a, h1a, h0b, h1b, h0c, h1c;
        hsum(sb[cur][rstart - 1][c], sb[cur][rstart - 1][c + 1], sb[cur][rstart - 1][c + 2], h0a, h1a);
        unsigned bm = sb[cur][rstart][c + 1];
        hsum(sb[cur][rstart][c], bm, sb[cur][rstart][c + 2], h0b, h1b);

        for (int r = rstart; r < rend; ++r) {
            unsigned nl = sb[cur][r + 1][c];
            unsigned nm = sb[cur][r + 1][c + 1];
            unsigned nr = sb[cur][r + 1][c + 2];
            hsum(nl, nm, nr, h0c, h1c);

            unsigned next = gol_combine(h0a, h1a, h0b, h1b, h0c, h1c, bm);
            if ((unsigned)(r0 - 8 + r) >= (unsigned)HH) next = 0u;
            sb[nxt][r][c + 1] = next;

            h0a = h0b; h1a = h1b;
            h0b = h0c; h1b = h1c;
            bm  = nm;
        }
        __syncthreads();
    }

    unsigned* dst = g_B + b * WORDS_PER_IMG;
    for (int idx = tid; idx < TH * 32; idx += 256) {
        int s  = idx >> 5;
        int cc = idx & 31;
        dst[(r0 + s) * WPR + cc] = sb[0][8 + s][cc + 1];
    }
}

// ---------------------------------------------------------------------------
// K3: vectorized unpack (bits -> float4 via funnelshift) + popc reduce +
// last-block finalize with self-reset. Block = 4096 cells (128 words).
// ---------------------------------------------------------------------------
__global__ __launch_bounds__(256) void k_unpack_reduce(float* __restrict__ out) {
    __shared__ int sh_live[8], sh_mism[8];
    int tid  = threadIdx.x;
    int lane = tid & 31;
    int wrp  = tid >> 5;
    int blk  = blockIdx.x;
    float* outs = out + 1;

    // ---- popc part: 128 words per block ----
    int live = 0, mism = 0;
    if (tid < 128) {
        unsigned w = g_B[blk * 128 + tid];
        unsigned t = g_T[blk * 128 + tid];
        live = __popc(w);
        mism = __popc(w ^ t);
    }

    // ---- vectorized unpack: quads at out-cell 3+4Q ----
    #pragma unroll
    for (int p = 0; p < 4; ++p) {
        int Q      = blk * 1024 + p * 256 + tid;      // global quad id
        int bitpos = 3 + 4 * Q;                       // global cell index
        int w0     = bitpos >> 5;
        int w1     = (w0 + 1 < NWORDS) ? w0 + 1 : w0;
        unsigned lo = g_B[w0];
        unsigned hi = g_B[w1];
        unsigned nib = __funnelshift_r(lo, hi, bitpos & 31) & 0xFu;
        if (Q < NQ) {
            float4 g;
            g.x = __uint_as_float((nib & 1u)        * 0x3f800000u);
            g.y = __uint_as_float(((nib >> 1) & 1u) * 0x3f800000u);
            g.z = __uint_as_float(((nib >> 2) & 1u) * 0x3f800000u);
            g.w = __uint_as_float(((nib >> 3) & 1u) * 0x3f800000u);
            *(float4*)(outs + 3 + 4 * Q) = g;
        } else {
            // the single skipped quad maps to the global tail cell
            outs[NCELLS - 1] = __uint_as_float((nib & 1u) * 0x3f800000u);
        }
        if (Q == 0) {                                  // global head (3 cells)
            unsigned w = g_B[0];
            outs[0] = __uint_as_float((w & 1u)        * 0x3f800000u);
            outs[1] = __uint_as_float(((w >> 1) & 1u) * 0x3f800000u);
            outs[2] = __uint_as_float(((w >> 2) & 1u) * 0x3f800000u);
        }
    }

    // ---- block reduce + atomics + last-block finalize/self-reset ----
    #pragma unroll
    for (int o = 16; o > 0; o >>= 1) {
        live += __shfl_down_sync(0xffffffffu, live, o);
        mism += __shfl_down_sync(0xffffffffu, mism, o);
    }
    if (lane == 0) { sh_live[wrp] = live; sh_mism[wrp] = mism; }
    __syncthreads();
    if (tid == 0) {
        int L = 0, M = 0;
        #pragma unroll
        for (int k = 0; k < 8; ++k) { L += sh_live[k]; M += sh_mism[k]; }
        atomicAdd(&g_live, (unsigned long long)L);
        atomicAdd(&g_mism, (unsigned long long)M);
        __threadfence();
        unsigned prev = atomicAdd(&g_done, 1u);
        if (prev == (unsigned)(NUNP - 1)) {
            unsigned long long mt = atomicAdd(&g_mism, 0ull);
            unsigned long long lt = atomicAdd(&g_live, 0ull);
            out[0]              = (float)((double)mt / (double)NCELLS);  // loss
            out[1 + 2 * NCELLS] = (float)lt;                             // live_cells
            out[2 + 2 * NCELLS] = mt ? 1.0f : 0.0f;                      // max_abs_error
            g_live = 0ull; g_mism = 0ull;                                // replay reset
            __threadfence();
            g_done = 0u;
        }
    }
}

extern "C" void kernel_launch(void* const* d_in, const int* in_sizes, int n_in,
                              void* d_out, int out_size) {
    const float* initial = (const float*)d_in[0];
    const float* target  = (const float*)d_in[1];
    (void)in_sizes; (void)n_in; (void)out_size;   // generations fixed at 8

    float* out = (float*)d_out;

    k_pack_ini<<<NCELLS / 2048, 256>>>(initial);
    k_life_tgt<<<NSIM + NCOPY, 256>>>(target, out);
    k_unpack_reduce<<<NUNP, 256>>>(out);
}